// round 4
// baseline (speedup 1.0000x reference)
#include <cuda_runtime.h>

#define C 64
#define MAXN 50000

// Scratch (allocation-free): degree -> deg_inv_sqrt (in place), and aggregation buffer.
// 16B alignment required for float4 vector atomics on g_agg.
__device__ __align__(16) float g_agg[MAXN * C];
__device__ float g_dis[MAXN];

// Zero deg + agg each call (deterministic; agg is accumulated via atomics).
__global__ void k_zero(int N) {
    int i = blockIdx.x * blockDim.x + threadIdx.x;
    if (i < N * C) g_agg[i] = 0.0f;
    if (i < N)     g_dis[i] = 0.0f;
}

// Stage 1: degree of target nodes.
__global__ void k_deg(const int* __restrict__ tgt, int E) {
    int i = blockIdx.x * blockDim.x + threadIdx.x;
    if (i < E) atomicAdd(&g_dis[tgt[i]], 1.0f);
}

// deg_inv_sqrt = clip(deg, 1)^-0.5
__global__ void k_rsqrt(int N) {
    int i = blockIdx.x * blockDim.x + threadIdx.x;
    if (i < N) g_dis[i] = rsqrtf(fmaxf(g_dis[i], 1.0f));
}

// Stages 2-4: gather x[src], scale by norm, scatter-add into agg[tgt].
// 16 lanes per edge; each lane handles one float4 (4 channels).
__global__ void k_scatter(const float* __restrict__ x,
                          const int* __restrict__ src,
                          const int* __restrict__ tgt, int E) {
    int t = blockIdx.x * blockDim.x + threadIdx.x;
    int e = t >> 4;
    if (e >= E) return;
    int q = t & 15;
    int s = src[e];
    int d = tgt[e];
    float norm = g_dis[s] * g_dis[d];
    float4 v = *(const float4*)(x + (size_t)s * C + q * 4);
    v.x *= norm; v.y *= norm; v.z *= norm; v.w *= norm;
    atomicAdd((float4*)(g_agg + (size_t)d * C + q * 4), v);
}

// Stages 5-6: out = relu(agg @ W^T + b).
// One thread per node row; W transposed into smem (Ws[k][j]) so the j-loop
// reads are LDS.128; agg rows staged through padded smem for conflict-free access.
__global__ void __launch_bounds__(64) k_gemm(const float* __restrict__ W,
                                             const float* __restrict__ b,
                                             float* __restrict__ out, int N) {
    __shared__ float Ws[C * C];        // Ws[k*64 + j] = W[j*64 + k]
    __shared__ float As[64][C + 1];    // 64 node rows, padded (bank-conflict-free)
    int tid = threadIdx.x;

    for (int idx = tid; idx < C * C; idx += 64) {
        int j = idx >> 6, k = idx & 63;
        Ws[k * C + j] = W[idx];
    }
    int base = blockIdx.x * 64;
    for (int i = 0; i < 64; i++) {
        int r = base + i;
        As[i][tid] = (r < N) ? g_agg[(size_t)r * C + tid] : 0.0f;
    }
    __syncthreads();

    float acc[C];
    #pragma unroll
    for (int j = 0; j < C; j++) acc[j] = b[j];

    for (int k = 0; k < C; k++) {
        float ak = As[tid][k];
        const float4* wr = (const float4*)(Ws + k * C);
        #pragma unroll
        for (int j4 = 0; j4 < 16; j4++) {
            float4 w = wr[j4];
            acc[4 * j4 + 0] += ak * w.x;
            acc[4 * j4 + 1] += ak * w.y;
            acc[4 * j4 + 2] += ak * w.z;
            acc[4 * j4 + 3] += ak * w.w;
        }
    }

    int node = base + tid;
    if (node < N) {
        float4* o = (float4*)(out + (size_t)node * C);
        #pragma unroll
        for (int j4 = 0; j4 < 16; j4++) {
            float4 r;
            r.x = fmaxf(acc[4 * j4 + 0], 0.0f);
            r.y = fmaxf(acc[4 * j4 + 1], 0.0f);
            r.z = fmaxf(acc[4 * j4 + 2], 0.0f);
            r.w = fmaxf(acc[4 * j4 + 3], 0.0f);
            o[j4] = r;
        }
    }
}

extern "C" void kernel_launch(void* const* d_in, const int* in_sizes, int n_in,
                              void* d_out, int out_size) {
    const float* x   = (const float*)d_in[0];
    const int*   ei  = (const int*)d_in[1];     // int32 (JAX default int), [2, E] row-major
    const float* W   = (const float*)d_in[2];
    const float* b   = (const float*)d_in[3];
    float*       out = (float*)d_out;

    int N = in_sizes[0] / C;     // 50000
    int E = in_sizes[1] / 2;     // 800000
    const int* src = ei;
    const int* tgt = ei + E;

    k_zero<<<(N * C + 255) / 256, 256>>>(N);
    k_deg<<<(E + 255) / 256, 256>>>(tgt, E);
    k_rsqrt<<<(N + 255) / 256, 256>>>(N);

    long long T = (long long)E * 16;
    k_scatter<<<(int)((T + 255) / 256), 256>>>(x, src, tgt, E);

    k_gemm<<<(N + 63) / 64, 64>>>(W, b, out, N);
}

// round 6
// speedup vs baseline: 1.0988x; 1.0988x over previous
#include <cuda_runtime.h>

#define C 64
#define MAXN 50000
#define MAXE 800000

// Scratch (allocation-free, graph-safe).
__device__ int   g_cnt[MAXN];                     // per-target degree
__device__ int   g_off[MAXN];                     // exclusive CSR offsets
__device__ int   g_cur[MAXN];                     // fill cursors
__device__ float g_dis[MAXN];                     // deg_inv_sqrt
__device__ int   g_srcid[MAXE];                   // CSR: source node per slot
__device__ int   g_bsum[256];                     // block sums for scan
__device__ __align__(16) float g_agg[MAXN * C];   // aggregated features

// Zero degree counts (only buffer that needs zeroing; agg is fully overwritten).
__global__ void k_zero(int N) {
    int i = blockIdx.x * blockDim.x + threadIdx.x;
    if (i < N) g_cnt[i] = 0;
}

// Stage 1: degree histogram of target nodes.
__global__ void k_deg(const int* __restrict__ tgt, int E) {
    int i = blockIdx.x * blockDim.x + threadIdx.x;
    if (i < E) atomicAdd(&g_cnt[tgt[i]], 1);
}

// Scan phase A: per-block exclusive scan of g_cnt (256 elems/block), block totals out.
__global__ void __launch_bounds__(256) k_scanA(int N) {
    __shared__ int sh[256];
    int t = threadIdx.x;
    int i = blockIdx.x * 256 + t;
    int v = (i < N) ? g_cnt[i] : 0;
    sh[t] = v;
    __syncthreads();
    for (int d = 1; d < 256; d <<= 1) {
        int u = (t >= d) ? sh[t - d] : 0;
        __syncthreads();
        sh[t] += u;
        __syncthreads();
    }
    if (i < N) g_off[i] = sh[t] - v;                 // exclusive within block
    if (t == 255) g_bsum[blockIdx.x] = sh[t];        // inclusive block total
}

// Scan phase B: exclusive scan of block totals (single block; nb <= 256).
__global__ void __launch_bounds__(256) k_scanB(int nb) {
    __shared__ int sh[256];
    int t = threadIdx.x;
    int v = (t < nb) ? g_bsum[t] : 0;
    sh[t] = v;
    __syncthreads();
    for (int d = 1; d < 256; d <<= 1) {
        int u = (t >= d) ? sh[t - d] : 0;
        __syncthreads();
        sh[t] += u;
        __syncthreads();
    }
    if (t < nb) g_bsum[t] = sh[t] - v;               // exclusive
}

// Scan phase C: finalize offsets, init cursors, compute deg_inv_sqrt.
__global__ void k_scanC(int N) {
    int i = blockIdx.x * 256 + threadIdx.x;
    if (i >= N) return;
    int o = g_off[i] + g_bsum[blockIdx.x];
    g_off[i] = o;
    g_cur[i] = o;
    g_dis[i] = rsqrtf(fmaxf((float)g_cnt[i], 1.0f));
}

// CSR fill: slot each edge's source id under its target.
__global__ void k_fill(const int* __restrict__ src, const int* __restrict__ tgt, int E) {
    int i = blockIdx.x * blockDim.x + threadIdx.x;
    if (i >= E) return;
    int pos = atomicAdd(&g_cur[tgt[i]], 1);
    g_srcid[pos] = src[i];
}

// Stages 2-4 without atomics: one warp per target node.
// 32 lanes hold 2 channels each; agg[n] = dis[n] * sum_e dis[src_e] * x[src_e].
__global__ void k_agg(const float* __restrict__ x, int N) {
    int w = (blockIdx.x * blockDim.x + threadIdx.x) >> 5;
    int lane = threadIdx.x & 31;
    if (w >= N) return;
    int off = g_off[w];
    int cnt = g_cnt[w];
    float a0 = 0.0f, a1 = 0.0f;
    int i = 0;
    for (; i + 2 <= cnt; i += 2) {           // unroll-2 for load-level parallelism
        int s0 = g_srcid[off + i];
        int s1 = g_srcid[off + i + 1];
        float w0 = g_dis[s0];
        float w1 = g_dis[s1];
        float2 v0 = *(const float2*)(x + (size_t)s0 * C + lane * 2);
        float2 v1 = *(const float2*)(x + (size_t)s1 * C + lane * 2);
        a0 += w0 * v0.x + w1 * v1.x;
        a1 += w0 * v0.y + w1 * v1.y;
    }
    if (i < cnt) {
        int s = g_srcid[off + i];
        float ws = g_dis[s];
        float2 v = *(const float2*)(x + (size_t)s * C + lane * 2);
        a0 += ws * v.x;
        a1 += ws * v.y;
    }
    float dn = g_dis[w];
    float2 r;
    r.x = a0 * dn;
    r.y = a1 * dn;
    *(float2*)(g_agg + (size_t)w * C + lane * 2) = r;
}

// Stages 5-6: out = relu(agg @ W^T + b). 64 threads = 64 node rows per block.
__global__ void __launch_bounds__(64) k_gemm(const float* __restrict__ W,
                                             const float* __restrict__ b,
                                             float* __restrict__ out, int N) {
    __shared__ float Ws[C * C];        // Ws[k*64 + j] = W[j*64 + k]
    __shared__ float As[64][C + 1];    // padded: conflict-free column reads
    int tid = threadIdx.x;

    for (int idx = tid; idx < C * C; idx += 64) {
        int j = idx >> 6, k = idx & 63;
        Ws[k * C + j] = W[idx];
    }
    int base = blockIdx.x * 64;
    for (int idx = tid; idx < 64 * 16; idx += 64) {   // float4-vectorized staging
        int i = idx >> 4, j4 = idx & 15;
        int r = base + i;
        float4 v = (r < N) ? ((const float4*)(g_agg + (size_t)r * C))[j4]
                           : make_float4(0.f, 0.f, 0.f, 0.f);
        As[i][j4 * 4 + 0] = v.x;
        As[i][j4 * 4 + 1] = v.y;
        As[i][j4 * 4 + 2] = v.z;
        As[i][j4 * 4 + 3] = v.w;
    }
    __syncthreads();

    float acc[C];
    #pragma unroll
    for (int j = 0; j < C; j++) acc[j] = b[j];

    for (int k = 0; k < C; k++) {
        float ak = As[tid][k];
        const float4* wr = (const float4*)(Ws + k * C);
        #pragma unroll
        for (int j4 = 0; j4 < 16; j4++) {
            float4 w = wr[j4];
            acc[4 * j4 + 0] += ak * w.x;
            acc[4 * j4 + 1] += ak * w.y;
            acc[4 * j4 + 2] += ak * w.z;
            acc[4 * j4 + 3] += ak * w.w;
        }
    }

    int node = base + tid;
    if (node < N) {
        float4* o = (float4*)(out + (size_t)node * C);
        #pragma unroll
        for (int j4 = 0; j4 < 16; j4++) {
            float4 r;
            r.x = fmaxf(acc[4 * j4 + 0], 0.0f);
            r.y = fmaxf(acc[4 * j4 + 1], 0.0f);
            r.z = fmaxf(acc[4 * j4 + 2], 0.0f);
            r.w = fmaxf(acc[4 * j4 + 3], 0.0f);
            o[j4] = r;
        }
    }
}

extern "C" void kernel_launch(void* const* d_in, const int* in_sizes, int n_in,
                              void* d_out, int out_size) {
    const float* x   = (const float*)d_in[0];
    const int*   ei  = (const int*)d_in[1];     // int32, [2, E] row-major
    const float* W   = (const float*)d_in[2];
    const float* b   = (const float*)d_in[3];
    float*       out = (float*)d_out;

    int N = in_sizes[0] / C;     // 50000
    int E = in_sizes[1] / 2;     // 800000
    const int* src = ei;
    const int* tgt = ei + E;
    int nb = (N + 255) / 256;    // scan blocks (196 <= 256)

    k_zero<<<(N + 255) / 256, 256>>>(N);
    k_deg<<<(E + 255) / 256, 256>>>(tgt, E);
    k_scanA<<<nb, 256>>>(N);
    k_scanB<<<1, 256>>>(nb);
    k_scanC<<<nb, 256>>>(N);
    k_fill<<<(E + 255) / 256, 256>>>(src, tgt, E);

    long long T = (long long)N * 32;
    k_agg<<<(int)((T + 255) / 256), 256>>>(x, N);

    k_gemm<<<(N + 63) / 64, 64>>>(W, b, out, N);
}